// round 1
// baseline (speedup 1.0000x reference)
#include <cuda_runtime.h>
#include <cstdint>

// Problem constants
#define BB 8
#define NN 256
#define FF 64      // OUT_F == OUT_E == IN_F
#define KE 32      // IN_E
#define KN 64      // IN_F

typedef unsigned long long u64;

// ---------- packed f32x2 helpers (Blackwell) ----------
__device__ __forceinline__ u64 ffma2(u64 a, u64 b, u64 c) {
    u64 d;
    asm("fma.rn.f32x2 %0, %1, %2, %3;" : "=l"(d) : "l"(a), "l"(b), "l"(c));
    return d;
}
__device__ __forceinline__ u64 fmul2(u64 a, u64 b) {
    u64 d;
    asm("mul.rn.f32x2 %0, %1, %2;" : "=l"(d) : "l"(a), "l"(b));
    return d;
}
__device__ __forceinline__ u64 fadd2(u64 a, u64 b) {
    u64 d;
    asm("add.rn.f32x2 %0, %1, %2;" : "=l"(d) : "l"(a), "l"(b));
    return d;
}
__device__ __forceinline__ u64 pack2(float lo, float hi) {
    u64 r;
    asm("mov.b64 %0, {%1, %2};" : "=l"(r) : "f"(lo), "f"(hi));
    return r;
}
__device__ __forceinline__ float2 unpack2(u64 v) {
    float2 r;
    asm("mov.b64 {%0, %1}, %2;" : "=f"(r.x), "=f"(r.y) : "l"(v));
    return r;
}

// ---------- scratch (no cudaMalloc allowed) ----------
// node_x stored pair-major: g_nodexP[(b*32 + f/2)*256 + m] = (nx[b][m][f], nx[b][m][f+1])
__device__ float2 g_nodexP[BB * 32 * NN];          // 512 KB
__device__ float  g_rsx[BB * NN * FF];             // relu(node_sx), 512 KB

// ============================================================
// Kernel 1: node projections  node_x = emb@W_node + b_node (raw, pair-major)
//                             rsx    = relu(emb@W_nodes + b_nodes)
// grid 512, block 256: CTA handles 4 rows of [2048, 64]
// ============================================================
__global__ void __launch_bounds__(256) node_proj_kernel(
    const float* __restrict__ emb_node,
    const float* __restrict__ W_node, const float* __restrict__ b_node,
    const float* __restrict__ W_nodes, const float* __restrict__ b_nodes)
{
    __shared__ float wsm0[KN * FF];   // 16 KB
    __shared__ float wsm1[KN * FF];   // 16 KB
    __shared__ float rsm[4 * KN];     // 1 KB

    const int tid = threadIdx.x;
    const int row0 = blockIdx.x * 4;

    {
        const float4* w0 = (const float4*)W_node;
        const float4* w1 = (const float4*)W_nodes;
        float4* s0 = (float4*)wsm0;
        float4* s1 = (float4*)wsm1;
        #pragma unroll
        for (int i = tid; i < KN * FF / 4; i += 256) { s0[i] = w0[i]; s1[i] = w1[i]; }
        if (tid < 64)
            ((float4*)rsm)[tid] = ((const float4*)(emb_node + (size_t)row0 * KN))[tid];
    }
    __syncthreads();

    const int rl = tid >> 6;       // local row 0..3
    const int f  = tid & 63;

    float nx = b_node[f];
    float sx = b_nodes[f];
    #pragma unroll
    for (int k = 0; k < KN; k++) {
        float a = rsm[rl * KN + k];
        nx = fmaf(a, wsm0[k * FF + f], nx);
        sx = fmaf(a, wsm1[k * FF + f], sx);
    }

    const int g1 = row0 + rl;          // global row = b*256 + n
    const int b = g1 >> 8;
    const int n = g1 & 255;
    // pair-major store of node_x
    ((float*)g_nodexP)[((size_t)(b * 32 + (f >> 1)) * NN + n) * 2 + (f & 1)] = nx;
    g_rsx[(size_t)g1 * FF + f] = fmaxf(sx, 0.0f);
}

// ============================================================
// Kernel 2: per (b,n) CTA —
//   edge_x[m,f] = emb_edge[b,n,m,:] @ W_edge + b_edge   (f32x2 register-blocked)
//   edge_out    = relu(edge_x)
//   node_out    = relu(sum_m A[b,n,m]*edge_x[m,f]*node_x[b,m,f]) + rsx[b,n,f]
// grid 2048, block 256 (8 warps: 2 m-halves x 4 f-quarters)
// thread: 4 m-rows (stride 32) x 8 f-pairs (16 channels)
// ============================================================
__global__ void __launch_bounds__(256, 2) edge_kernel(
    const float* __restrict__ A,
    const float* __restrict__ emb_edge,
    const float* __restrict__ W_edge,
    const float* __restrict__ b_edge,
    float* __restrict__ out)
{
    __shared__ float esm[NN * 36];      // 36864 B, emb_edge rows padded to 36 floats
    __shared__ float wsm[KE * FF];      // 8192 B
    __shared__ float Asm[NN];           // 1024 B
    __shared__ float besm[FF];          // 256 B
    __shared__ float2 red[8 * 8];       // 512 B

    const int g   = blockIdx.x;         // b*256 + n
    const int b   = g >> 8;
    const int tid = threadIdx.x;

    // --- stage emb_edge [256 x 32] -> padded stride-36 smem (coalesced) ---
    {
        const float4* src = (const float4*)(emb_edge + (size_t)g * (NN * KE));
        #pragma unroll
        for (int i = 0; i < 8; i++) {
            int e4  = tid + i * 256;        // 0..2047 float4s
            int row = e4 >> 3;              // 8 float4 per row
            int c4  = e4 & 7;
            *(float4*)&esm[row * 36 + c4 * 4] = src[e4];
        }
        const float4* wsrc = (const float4*)W_edge;
        #pragma unroll
        for (int i = tid; i < KE * FF / 4; i += 256) ((float4*)wsm)[i] = wsrc[i];
        if (tid < 64) ((float4*)Asm)[tid] = ((const float4*)(A + (size_t)g * NN))[tid];
        if (tid < 64) besm[tid] = b_edge[tid];
    }
    __syncthreads();

    const int lane = tid & 31;
    const int w    = tid >> 5;
    const int mh   = w >> 2;            // m half: 0/1
    const int fq   = w & 3;             // f quarter: 16 channels
    const int mbase = mh * 128 + lane;  // m = mbase + mi*32

    // --- accumulators init with bias pairs ---
    u64 acc[4][8];
    {
        u64 bini[8];
        #pragma unroll
        for (int fp = 0; fp < 8; fp++)
            bini[fp] = pack2(besm[fq * 16 + 2 * fp], besm[fq * 16 + 2 * fp + 1]);
        #pragma unroll
        for (int mi = 0; mi < 4; mi++)
            #pragma unroll
            for (int fp = 0; fp < 8; fp++)
                acc[mi][fp] = bini[fp];
    }

    // --- main GEMM: 32k x (4m x 16f) per thread via f32x2 FMA ---
    #pragma unroll
    for (int k4 = 0; k4 < 8; k4++) {
        float4 av[4];
        #pragma unroll
        for (int mi = 0; mi < 4; mi++)
            av[mi] = *(const float4*)&esm[(mbase + mi * 32) * 36 + k4 * 4];
        #pragma unroll
        for (int kk = 0; kk < 4; kk++) {
            const int k = k4 * 4 + kk;
            const float4* wp4 = (const float4*)&wsm[k * FF + fq * 16];
            u64 wv[8];
            #pragma unroll
            for (int q = 0; q < 4; q++) {
                float4 t = wp4[q];
                wv[2 * q]     = pack2(t.x, t.y);
                wv[2 * q + 1] = pack2(t.z, t.w);
            }
            #pragma unroll
            for (int mi = 0; mi < 4; mi++) {
                float a = (kk == 0) ? av[mi].x : (kk == 1) ? av[mi].y
                        : (kk == 2) ? av[mi].z : av[mi].w;
                u64 a2 = pack2(a, a);
                #pragma unroll
                for (int fp = 0; fp < 8; fp++)
                    acc[mi][fp] = ffma2(a2, wv[fp], acc[mi][fp]);
            }
        }
    }

    // --- epilogue: aggregation contribution + relu store of edge_out ---
    float* eout = out + (BB * NN * FF) + (size_t)g * (NN * FF);
    const float2* nxp = (const float2*)g_nodexP;

    u64 c2[8];
    #pragma unroll
    for (int fp = 0; fp < 8; fp++) c2[fp] = 0ull;

    #pragma unroll
    for (int mi = 0; mi < 4; mi++) {
        const int m = mbase + mi * 32;
        const float Am = Asm[m];
        const u64 A2 = pack2(Am, Am);

        float2 nx[8];
        #pragma unroll
        for (int fp = 0; fp < 8; fp++)
            nx[fp] = nxp[(size_t)(b * 32 + fq * 8 + fp) * NN + m];

        #pragma unroll
        for (int fp = 0; fp < 8; fp++) {
            u64 t = fmul2(A2, pack2(nx[fp].x, nx[fp].y));
            c2[fp] = ffma2(t, acc[mi][fp], c2[fp]);     // += A * nx * edge_x
        }

        // store relu(edge_x): 64 contiguous bytes per m per thread
        #pragma unroll
        for (int q = 0; q < 4; q++) {
            float2 p0 = unpack2(acc[mi][2 * q]);
            float2 p1 = unpack2(acc[mi][2 * q + 1]);
            float4 o = make_float4(fmaxf(p0.x, 0.0f), fmaxf(p0.y, 0.0f),
                                   fmaxf(p1.x, 0.0f), fmaxf(p1.y, 0.0f));
            *(float4*)&eout[m * FF + fq * 16 + q * 4] = o;
        }
    }

    // --- warp butterfly reduction over 32 lanes (sums 128 m per warp) ---
    #pragma unroll
    for (int d = 16; d; d >>= 1) {
        #pragma unroll
        for (int fp = 0; fp < 8; fp++)
            c2[fp] = fadd2(c2[fp], __shfl_xor_sync(0xffffffffu, c2[fp], d));
    }
    if (lane == 0) {
        #pragma unroll
        for (int fp = 0; fp < 8; fp++)
            red[w * 8 + fp] = unpack2(c2[fp]);
    }
    __syncthreads();

    // --- combine the two m-halves, final node_out ---
    if (tid < 64) {
        const int f   = tid;
        const int fq2 = f >> 4;
        const int fp2 = (f >> 1) & 7;
        const int h   = f & 1;
        float2 r0 = red[fq2 * 8 + fp2];         // warp (mh=0, fq2)
        float2 r1 = red[(4 + fq2) * 8 + fp2];   // warp (mh=1, fq2)
        float v = (h ? r0.y : r0.x) + (h ? r1.y : r1.x);
        out[(size_t)g * FF + f] = fmaxf(v, 0.0f) + g_rsx[(size_t)g * FF + f];
    }
}

// ============================================================
// launch
// ============================================================
extern "C" void kernel_launch(void* const* d_in, const int* in_sizes, int n_in,
                              void* d_out, int out_size)
{
    const float* A        = (const float*)d_in[0];
    const float* emb_node = (const float*)d_in[1];
    const float* emb_edge = (const float*)d_in[2];
    const float* W_node   = (const float*)d_in[3];
    const float* b_node   = (const float*)d_in[4];
    const float* W_nodes  = (const float*)d_in[5];
    const float* b_nodes  = (const float*)d_in[6];
    const float* W_edge   = (const float*)d_in[7];
    const float* b_edge   = (const float*)d_in[8];
    float* out = (float*)d_out;

    node_proj_kernel<<<512, 256>>>(emb_node, W_node, b_node, W_nodes, b_nodes);
    edge_kernel<<<2048, 256>>>(A, emb_edge, W_edge, b_edge, out);
}

// round 2
// speedup vs baseline: 1.0367x; 1.0367x over previous
#include <cuda_runtime.h>
#include <cstdint>

// Problem constants
#define BB 8
#define NN 256
#define FF 64      // OUT_F == OUT_E == IN_F
#define KE 32      // IN_E
#define KN 64      // IN_F
#define HROWS 128  // m-rows per edge CTA (each (b,n) split across 2 CTAs)

typedef unsigned long long u64;

// ---------- packed f32x2 helpers (Blackwell) ----------
__device__ __forceinline__ u64 ffma2(u64 a, u64 b, u64 c) {
    u64 d;
    asm("fma.rn.f32x2 %0, %1, %2, %3;" : "=l"(d) : "l"(a), "l"(b), "l"(c));
    return d;
}
__device__ __forceinline__ u64 fmul2(u64 a, u64 b) {
    u64 d;
    asm("mul.rn.f32x2 %0, %1, %2;" : "=l"(d) : "l"(a), "l"(b));
    return d;
}
__device__ __forceinline__ u64 fadd2(u64 a, u64 b) {
    u64 d;
    asm("add.rn.f32x2 %0, %1, %2;" : "=l"(d) : "l"(a), "l"(b));
    return d;
}
__device__ __forceinline__ u64 pack2(float lo, float hi) {
    u64 r;
    asm("mov.b64 %0, {%1, %2};" : "=l"(r) : "f"(lo), "f"(hi));
    return r;
}
__device__ __forceinline__ float2 unpack2(u64 v) {
    float2 r;
    asm("mov.b64 {%0, %1}, %2;" : "=f"(r.x), "=f"(r.y) : "l"(v));
    return r;
}

// ---------- cp.async helpers ----------
__device__ __forceinline__ uint32_t smem_u32(const void* p) {
    uint32_t a;
    asm("{ .reg .u64 t; cvta.to.shared.u64 t, %1; cvt.u32.u64 %0, t; }" : "=r"(a) : "l"(p));
    return a;
}
__device__ __forceinline__ void cpa16(uint32_t saddr, const void* g) {
    asm volatile("cp.async.cg.shared.global [%0], [%1], 16;" :: "r"(saddr), "l"(g));
}
__device__ __forceinline__ void cpa_commit_wait() {
    asm volatile("cp.async.commit_group;");
    asm volatile("cp.async.wait_group 0;");
}

// ---------- scratch (no cudaMalloc allowed) ----------
// node_x pair-major: g_nodexP[(b*32 + f/2)*256 + m] = (nx[b][m][2fp], nx[b][m][2fp+1])
__device__ float2 g_nodexP[BB * 32 * NN];           // 512 KB
__device__ float  g_rsx[BB * NN * FF];              // relu(node_sx), 512 KB
__device__ float2 g_part[2 * BB * NN * 32];         // per-half partial agg sums, 1 MB

// ============================================================
// Kernel 1: node projections
// ============================================================
__global__ void __launch_bounds__(256) node_proj_kernel(
    const float* __restrict__ emb_node,
    const float* __restrict__ W_node, const float* __restrict__ b_node,
    const float* __restrict__ W_nodes, const float* __restrict__ b_nodes)
{
    __shared__ float wsm0[KN * FF];
    __shared__ float wsm1[KN * FF];
    __shared__ float rsm[4 * KN];

    const int tid = threadIdx.x;
    const int row0 = blockIdx.x * 4;

    {
        const float4* w0 = (const float4*)W_node;
        const float4* w1 = (const float4*)W_nodes;
        float4* s0 = (float4*)wsm0;
        float4* s1 = (float4*)wsm1;
        #pragma unroll
        for (int i = tid; i < KN * FF / 4; i += 256) { s0[i] = w0[i]; s1[i] = w1[i]; }
        if (tid < 64)
            ((float4*)rsm)[tid] = ((const float4*)(emb_node + (size_t)row0 * KN))[tid];
    }
    __syncthreads();

    const int rl = tid >> 6;
    const int f  = tid & 63;

    float nx = b_node[f];
    float sx = b_nodes[f];
    #pragma unroll
    for (int k = 0; k < KN; k++) {
        float a = rsm[rl * KN + k];
        nx = fmaf(a, wsm0[k * FF + f], nx);
        sx = fmaf(a, wsm1[k * FF + f], sx);
    }

    const int g1 = row0 + rl;
    const int b = g1 >> 8;
    const int n = g1 & 255;
    ((float*)g_nodexP)[((size_t)(b * 32 + (f >> 1)) * NN + n) * 2 + (f & 1)] = nx;
    g_rsx[(size_t)g1 * FF + f] = fmaxf(sx, 0.0f);
}

// ============================================================
// Kernel 2: per (b,n,half) CTA — 128 m-rows x 64 f
//   edge_x = emb_edge @ W_edge + b_edge      (f32x2 FMA)
//   edge_out = relu(edge_x)
//   partial node agg = sum_m A*edge_x*node_x  -> g_part
// block 256 = 8 warps; warp w owns f-pairs [4w, 4w+4); lane+32*mi -> m
// ============================================================
__global__ void __launch_bounds__(256, 3) edge_kernel(
    const float* __restrict__ A,
    const float* __restrict__ emb_edge,
    const float* __restrict__ W_edge,
    const float* __restrict__ b_edge,
    float* __restrict__ out)
{
    __shared__ float esm[HROWS * 36];   // 18432 B, rows padded to 36 floats
    __shared__ float wsm[KE * FF];      // 8192 B
    __shared__ float Asm[HROWS];        // 512 B
    __shared__ float besm[FF];          // 256 B

    const int g2   = blockIdx.x;        // (b*256+n)*2 + half
    const int g    = g2 >> 1;
    const int half = g2 & 1;
    const int b    = g >> 8;
    const int tid  = threadIdx.x;

    // --- stage via cp.async ---
    {
        const float4* src = (const float4*)(emb_edge + ((size_t)g * NN + half * HROWS) * KE);
        uint32_t esm_s = smem_u32(esm);
        #pragma unroll
        for (int i = 0; i < 4; i++) {
            int e4  = tid + i * 256;            // 0..1023 float4
            int row = e4 >> 3;
            int c4  = e4 & 7;
            cpa16(esm_s + (row * 36 + c4 * 4) * 4, src + e4);
        }
        uint32_t wsm_s = smem_u32(wsm);
        const float4* wsrc = (const float4*)W_edge;
        cpa16(wsm_s + tid * 16, wsrc + tid);
        cpa16(wsm_s + (tid + 256) * 16, wsrc + tid + 256);
        if (tid < 32)
            cpa16(smem_u32(Asm) + tid * 16,
                  (const float4*)(A + (size_t)g * NN + half * HROWS) + tid);
        if (tid < 16)
            cpa16(smem_u32(besm) + tid * 16, (const float4*)b_edge + tid);
        cpa_commit_wait();
    }
    __syncthreads();

    const int lane = tid & 31;
    const int w    = tid >> 5;          // warp: f-pairs 4w..4w+3 (f = 8w..8w+7)

    // --- accumulators init with bias pairs ---
    u64 acc[4][4];
    {
        u64 bini[4];
        #pragma unroll
        for (int q = 0; q < 4; q++)
            bini[q] = pack2(besm[w * 8 + 2 * q], besm[w * 8 + 2 * q + 1]);
        #pragma unroll
        for (int mi = 0; mi < 4; mi++)
            #pragma unroll
            for (int q = 0; q < 4; q++)
                acc[mi][q] = bini[q];
    }

    // --- GEMM: 32k x (4m x 8f) per thread ---
    #pragma unroll
    for (int k4 = 0; k4 < 8; k4++) {
        float4 av[4];
        #pragma unroll
        for (int mi = 0; mi < 4; mi++)
            av[mi] = *(const float4*)&esm[(lane + mi * 32) * 36 + k4 * 4];
        #pragma unroll
        for (int kk = 0; kk < 4; kk++) {
            const int k = k4 * 4 + kk;
            float4 t0 = *(const float4*)&wsm[k * FF + w * 8];
            float4 t1 = *(const float4*)&wsm[k * FF + w * 8 + 4];
            u64 wv[4];
            wv[0] = pack2(t0.x, t0.y);
            wv[1] = pack2(t0.z, t0.w);
            wv[2] = pack2(t1.x, t1.y);
            wv[3] = pack2(t1.z, t1.w);
            #pragma unroll
            for (int mi = 0; mi < 4; mi++) {
                float a = (kk == 0) ? av[mi].x : (kk == 1) ? av[mi].y
                        : (kk == 2) ? av[mi].z : av[mi].w;
                u64 a2 = pack2(a, a);
                #pragma unroll
                for (int q = 0; q < 4; q++)
                    acc[mi][q] = ffma2(a2, wv[q], acc[mi][q]);
            }
        }
    }

    // --- epilogue: aggregation + relu edge_out stores ---
    float* eout = out + (BB * NN * FF) + (size_t)g * (NN * FF);
    const float2* nxp = (const float2*)g_nodexP;

    u64 c2[4];
    #pragma unroll
    for (int q = 0; q < 4; q++) c2[q] = 0ull;

    #pragma unroll
    for (int mi = 0; mi < 4; mi++) {
        const int ml = lane + mi * 32;        // local row
        const int m  = half * HROWS + ml;     // global row
        const float Am = Asm[ml];
        const u64 A2 = pack2(Am, Am);

        #pragma unroll
        for (int q = 0; q < 4; q++) {
            float2 nx = nxp[(size_t)(b * 32 + w * 4 + q) * NN + m];
            u64 t = fmul2(A2, pack2(nx.x, nx.y));
            c2[q] = ffma2(t, acc[mi][q], c2[q]);   // += A * nx * edge_x
        }

        float2 p0 = unpack2(acc[mi][0]);
        float2 p1 = unpack2(acc[mi][1]);
        float2 p2 = unpack2(acc[mi][2]);
        float2 p3 = unpack2(acc[mi][3]);
        float4 o0 = make_float4(fmaxf(p0.x, 0.f), fmaxf(p0.y, 0.f),
                                fmaxf(p1.x, 0.f), fmaxf(p1.y, 0.f));
        float4 o1 = make_float4(fmaxf(p2.x, 0.f), fmaxf(p2.y, 0.f),
                                fmaxf(p3.x, 0.f), fmaxf(p3.y, 0.f));
        *(float4*)&eout[(size_t)m * FF + w * 8]     = o0;
        *(float4*)&eout[(size_t)m * FF + w * 8 + 4] = o1;
    }

    // --- warp butterfly over 32 lanes (sums this CTA's 128 m) ---
    #pragma unroll
    for (int d = 16; d; d >>= 1) {
        #pragma unroll
        for (int q = 0; q < 4; q++)
            c2[q] = fadd2(c2[q], __shfl_xor_sync(0xffffffffu, c2[q], d));
    }
    if (lane == 0) {
        #pragma unroll
        for (int q = 0; q < 4; q++)
            g_part[(size_t)g2 * 32 + w * 4 + q] = unpack2(c2[q]);
    }
}

// ============================================================
// Kernel 3: combine halves -> node_out = relu(p0+p1) + rsx
// 65536 f-pairs total
// ============================================================
__global__ void __launch_bounds__(256) finish_kernel(float* __restrict__ out)
{
    const int idx = blockIdx.x * 256 + threadIdx.x;   // 0..65535
    const int g  = idx >> 5;
    const int fp = idx & 31;
    float2 a = g_part[(size_t)(2 * g) * 32 + fp];
    float2 b = g_part[(size_t)(2 * g + 1) * 32 + fp];
    float2 r = *(const float2*)&g_rsx[(size_t)g * FF + 2 * fp];
    float2 o;
    o.x = fmaxf(a.x + b.x, 0.0f) + r.x;
    o.y = fmaxf(a.y + b.y, 0.0f) + r.y;
    *(float2*)&out[(size_t)g * FF + 2 * fp] = o;
}

// ============================================================
// launch
// ============================================================
extern "C" void kernel_launch(void* const* d_in, const int* in_sizes, int n_in,
                              void* d_out, int out_size)
{
    const float* A        = (const float*)d_in[0];
    const float* emb_node = (const float*)d_in[1];
    const float* emb_edge = (const float*)d_in[2];
    const float* W_node   = (const float*)d_in[3];
    const float* b_node   = (const float*)d_in[4];
    const float* W_nodes  = (const float*)d_in[5];
    const float* b_nodes  = (const float*)d_in[6];
    const float* W_edge   = (const float*)d_in[7];
    const float* b_edge   = (const float*)d_in[8];
    float* out = (float*)d_out;

    node_proj_kernel<<<512, 256>>>(emb_node, W_node, b_node, W_nodes, b_nodes);
    edge_kernel<<<2 * BB * NN, 256>>>(A, emb_edge, W_edge, b_edge, out);
    finish_kernel<<<256, 256>>>(out);
}

// round 3
// speedup vs baseline: 1.1951x; 1.1528x over previous
#include <cuda_runtime.h>
#include <cstdint>

// Problem constants
#define BB 8
#define NN 256
#define FF 64      // OUT_F == OUT_E
#define KE 32      // IN_E
#define KN 64      // IN_F
#define HROWS 128  // m-rows per edge CTA ((b,n) split across 2 CTAs)

typedef unsigned long long u64;

// ---------- packed f32x2 helpers (Blackwell) ----------
__device__ __forceinline__ u64 ffma2(u64 a, u64 b, u64 c) {
    u64 d;
    asm("fma.rn.f32x2 %0, %1, %2, %3;" : "=l"(d) : "l"(a), "l"(b), "l"(c));
    return d;
}
__device__ __forceinline__ u64 fmul2(u64 a, u64 b) {
    u64 d;
    asm("mul.rn.f32x2 %0, %1, %2;" : "=l"(d) : "l"(a), "l"(b));
    return d;
}
__device__ __forceinline__ u64 pack2(float lo, float hi) {
    u64 r;
    asm("mov.b64 %0, {%1, %2};" : "=l"(r) : "f"(lo), "f"(hi));
    return r;
}
__device__ __forceinline__ float2 unpack2(u64 v) {
    float2 r;
    asm("mov.b64 {%0, %1}, %2;" : "=f"(r.x), "=f"(r.y) : "l"(v));
    return r;
}

// ---------- cp.async helpers ----------
__device__ __forceinline__ uint32_t smem_u32(const void* p) {
    uint32_t a;
    asm("{ .reg .u64 t; cvta.to.shared.u64 t, %1; cvt.u32.u64 %0, t; }" : "=r"(a) : "l"(p));
    return a;
}
__device__ __forceinline__ void cpa16(uint32_t saddr, const void* g) {
    asm volatile("cp.async.cg.shared.global [%0], [%1], 16;" :: "r"(saddr), "l"(g));
}
__device__ __forceinline__ void cpa_commit_wait() {
    asm volatile("cp.async.commit_group;");
    asm volatile("cp.async.wait_group 0;");
}

// ---------- scratch ----------
__device__ float  g_nodex[BB * NN * FF];     // node_x, natural [b][m][f] layout
__device__ float  g_rsx[BB * NN * FF];       // relu(node_sx)
__device__ float2 g_part[2 * BB * NN * 32];  // per-half partial agg sums

// ============================================================
// Kernel 1: node projections. grid 256, block 256: CTA = 8 rows.
// thread computes rows (rl, rl+4) x channel f for both matrices.
// ============================================================
__global__ void __launch_bounds__(256) node_proj_kernel(
    const float* __restrict__ emb_node,
    const float* __restrict__ W_node, const float* __restrict__ b_node,
    const float* __restrict__ W_nodes, const float* __restrict__ b_nodes)
{
    __shared__ float wsm0[KN * FF];
    __shared__ float wsm1[KN * FF];
    __shared__ float rsm[8 * KN];

    const int tid = threadIdx.x;
    const int row0 = blockIdx.x * 8;

    {
        const float4* w0 = (const float4*)W_node;
        const float4* w1 = (const float4*)W_nodes;
        #pragma unroll
        for (int i = tid; i < KN * FF / 4; i += 256) {
            ((float4*)wsm0)[i] = w0[i];
            ((float4*)wsm1)[i] = w1[i];
        }
        if (tid < 128)
            ((float4*)rsm)[tid] = ((const float4*)(emb_node + (size_t)row0 * KN))[tid];
    }
    __syncthreads();

    const int rl = tid >> 6;       // 0..3
    const int f  = tid & 63;

    float nx0 = b_node[f], sx0 = b_nodes[f];
    float nx1 = nx0,       sx1 = sx0;
    #pragma unroll
    for (int k = 0; k < KN; k++) {
        float a0 = rsm[rl * KN + k];
        float a1 = rsm[(rl + 4) * KN + k];
        float w0 = wsm0[k * FF + f];
        float w1 = wsm1[k * FF + f];
        nx0 = fmaf(a0, w0, nx0);  sx0 = fmaf(a0, w1, sx0);
        nx1 = fmaf(a1, w0, nx1);  sx1 = fmaf(a1, w1, sx1);
    }

    const int ga = row0 + rl;
    const int gb = row0 + rl + 4;
    g_nodex[(size_t)ga * FF + f] = nx0;
    g_nodex[(size_t)gb * FF + f] = nx1;
    g_rsx[(size_t)ga * FF + f] = fmaxf(sx0, 0.0f);
    g_rsx[(size_t)gb * FF + f] = fmaxf(sx1, 0.0f);
}

// ============================================================
// Kernel 2: per (b,n,half) CTA — 128 m-rows x 64 f
//   block 512 = 16 warps; warp w owns rows [8w, 8w+8); lane owns f-pair (2l,2l+1)
//   Accumulators are k-split f32x2: acc = (even-k partial, odd-k partial).
//   All global accesses (edge store, node_x load) are lane-contiguous.
// ============================================================
__global__ void __launch_bounds__(512, 2) edge_kernel(
    const float* __restrict__ A,
    const float* __restrict__ emb_edge,
    const float* __restrict__ W_edge,
    const float* __restrict__ b_edge,
    float* __restrict__ out)
{
    __shared__ float  esm[HROWS * KE];     // 16384 B, a-tile (no pad: broadcast reads)
    __shared__ u64    wsm_t[16 * FF];      // 8192 B: [k2][f] = (W[2k2][f], W[2k2+1][f])
    __shared__ float  Asm[HROWS];          // 512 B
    __shared__ float  besm[FF];            // 256 B
    __shared__ float2 red[16 * 32];        // 4096 B

    const int g2   = blockIdx.x;           // (b*256+n)*2 + half
    const int g    = g2 >> 1;
    const int half = g2 & 1;
    const int b    = g >> 8;
    const int tid  = threadIdx.x;

    // --- stage ---
    {
        // emb_edge slice: 128 rows x 32 floats, contiguous -> cp.async straight copy
        const float4* src = (const float4*)(emb_edge + ((size_t)g * NN + half * HROWS) * KE);
        uint32_t esm_s = smem_u32(esm);
        cpa16(esm_s + tid * 16, src + tid);
        cpa16(esm_s + (tid + 512) * 16, src + tid + 512);

        // W transpose into k-pairs
        if (tid < 256) {
            const float4* W4 = (const float4*)W_edge;
            const int k2 = tid >> 4;       // 0..15
            const int c4 = tid & 15;       // f4 group
            float4 v0 = W4[(2 * k2) * 16 + c4];
            float4 v1 = W4[(2 * k2 + 1) * 16 + c4];
            u64* dst = &wsm_t[k2 * FF + c4 * 4];
            ((ulonglong2*)dst)[0] = make_ulonglong2(pack2(v0.x, v1.x), pack2(v0.y, v1.y));
            ((ulonglong2*)(dst + 2))[0] = make_ulonglong2(pack2(v0.z, v1.z), pack2(v0.w, v1.w));
        }
        if (tid < 32)
            ((float4*)Asm)[tid] = ((const float4*)(A + (size_t)g * NN + half * HROWS))[tid];
        if (tid < 16)
            ((float4*)besm)[tid] = ((const float4*)b_edge)[tid];
        cpa_commit_wait();
    }
    __syncthreads();

    const int lane  = tid & 31;
    const int w     = tid >> 5;            // 0..15
    const int rbase = w * 8;               // local row base

    // acc[r][j]: j=0 -> f=2l, j=1 -> f=2l+1; u64 = (even-k partial, odd-k partial)
    u64 acc[8][2];
    #pragma unroll
    for (int r = 0; r < 8; r++) { acc[r][0] = 0ull; acc[r][1] = 0ull; }

    const u64* esm64 = (const u64*)esm;    // row stride 16 u64

    // --- GEMM: per k4 load 4 k of W (2 k-pairs) for this lane's 2 f's ---
    #pragma unroll
    for (int k4 = 0; k4 < 8; k4++) {
        ulonglong2 wa = *(const ulonglong2*)&wsm_t[(2 * k4) * FF + 2 * lane];
        ulonglong2 wb = *(const ulonglong2*)&wsm_t[(2 * k4 + 1) * FF + 2 * lane];
        #pragma unroll
        for (int r = 0; r < 8; r++) {
            ulonglong2 a = *(const ulonglong2*)&esm64[(rbase + r) * 16 + 2 * k4];
            // a.x = (a[4k4], a[4k4+1]) ; a.y = (a[4k4+2], a[4k4+3])  (broadcast)
            acc[r][0] = ffma2(a.x, wa.x, acc[r][0]);
            acc[r][1] = ffma2(a.x, wa.y, acc[r][1]);
            acc[r][0] = ffma2(a.y, wb.x, acc[r][0]);
            acc[r][1] = ffma2(a.y, wb.y, acc[r][1]);
        }
    }

    // --- epilogue: coalesced stores + aggregation ---
    float* eout = out + (BB * NN * FF) + (size_t)g * (NN * FF);
    const float* nxb = g_nodex + (size_t)b * (NN * FF);
    const float2 bf = *(const float2*)&besm[2 * lane];

    u64 c2 = 0ull;
    #pragma unroll
    for (int r = 0; r < 8; r++) {
        const int ml = rbase + r;
        const int m  = half * HROWS + ml;      // node index 0..255
        const float Am = Asm[ml];

        float2 p0 = unpack2(acc[r][0]);
        float2 p1 = unpack2(acc[r][1]);
        float ex = p0.x + p0.y + bf.x;         // edge_x (pre-relu)
        float ey = p1.x + p1.y + bf.y;

        // coalesced relu store: warp covers 256 contiguous bytes
        float2 o = make_float2(fmaxf(ex, 0.0f), fmaxf(ey, 0.0f));
        *(float2*)&eout[(size_t)m * FF + 2 * lane] = o;

        // aggregation: c += A[m] * node_x[m][f] * edge_x[m][f]
        u64 nxu = *(const u64*)&nxb[(size_t)m * FF + 2 * lane];   // coalesced
        u64 t = fmul2(pack2(Am, Am), nxu);
        c2 = ffma2(t, pack2(ex, ey), c2);
    }

    // --- cross-warp reduction (16 warps, same lane = same f-pair) ---
    red[w * 32 + lane] = unpack2(c2);
    __syncthreads();
    if (tid < 32) {
        float2 s = red[tid];
        #pragma unroll
        for (int q = 1; q < 16; q++) {
            float2 v = red[q * 32 + tid];
            s.x += v.x; s.y += v.y;
        }
        g_part[(size_t)g2 * 32 + tid] = s;
    }
}

// ============================================================
// Kernel 3: combine halves -> node_out = relu(p0+p1) + rsx
// ============================================================
__global__ void __launch_bounds__(256) finish_kernel(float* __restrict__ out)
{
    const int idx = blockIdx.x * 256 + threadIdx.x;   // 0..65535
    const int g  = idx >> 5;
    const int fp = idx & 31;
    float2 a = g_part[(size_t)(2 * g) * 32 + fp];
    float2 b = g_part[(size_t)(2 * g + 1) * 32 + fp];
    float2 r = *(const float2*)&g_rsx[(size_t)g * FF + 2 * fp];
    float2 o;
    o.x = fmaxf(a.x + b.x, 0.0f) + r.x;
    o.y = fmaxf(a.y + b.y, 0.0f) + r.y;
    *(float2*)&out[(size_t)g * FF + 2 * fp] = o;
}

// ============================================================
// launch
// ============================================================
extern "C" void kernel_launch(void* const* d_in, const int* in_sizes, int n_in,
                              void* d_out, int out_size)
{
    const float* A        = (const float*)d_in[0];
    const float* emb_node = (const float*)d_in[1];
    const float* emb_edge = (const float*)d_in[2];
    const float* W_node   = (const float*)d_in[3];
    const float* b_node   = (const float*)d_in[4];
    const float* W_nodes  = (const float*)d_in[5];
    const float* b_nodes  = (const float*)d_in[6];
    const float* W_edge   = (const float*)d_in[7];
    const float* b_edge   = (const float*)d_in[8];
    float* out = (float*)d_out;

    node_proj_kernel<<<256, 256>>>(emb_node, W_node, b_node, W_nodes, b_nodes);
    edge_kernel<<<2 * BB * NN, 512>>>(A, emb_edge, W_edge, b_edge, out);
    finish_kernel<<<256, 256>>>(out);
}